// round 1
// baseline (speedup 1.0000x reference)
#include <cuda_runtime.h>

#define NEG_SLOPE 0.2f
#define LN_EPS 1e-5f

static const int MAXN = 50000;
static const int MAXE = 800000;

// Scratch (allocation-free: __device__ globals)
__device__ float g_xl[MAXN * 64];
__device__ float g_xr[MAXN * 64];
__device__ float g_aexp[(size_t)MAXE * 4];
__device__ float g_denom[MAXN * 4];
__device__ float g_acc[MAXN * 64];

__device__ __forceinline__ void red_add_v4(float* addr, float a, float b, float c, float d) {
    asm volatile("red.global.add.v4.f32 [%0], {%1,%2,%3,%4};"
                 :: "l"(addr), "f"(a), "f"(b), "f"(c), "f"(d) : "memory");
}

// K1: xl = x@Wl + bl, xr = x@Wr + br. Also zeroes acc/denom for this block's nodes.
// Block: 256 threads, 32 nodes. W resident in shared (32 KB), x rows staged 4 at a time.
__global__ void linear_kernel(const float* __restrict__ x,
                              const float* __restrict__ Wl, const float* __restrict__ bl,
                              const float* __restrict__ Wr, const float* __restrict__ br,
                              int n) {
    __shared__ float sWl[64 * 64];
    __shared__ float sWr[64 * 64];
    __shared__ float sx[4 * 64];
    int tid = threadIdx.x;
    for (int i = tid; i < 4096; i += 256) { sWl[i] = Wl[i]; sWr[i] = Wr[i]; }

    int base = blockIdx.x * 32;
    // zero accumulators for this block's node range
    for (int i = tid; i < 32 * 64; i += 256) {
        int node = base + (i >> 6);
        if (node < n) g_acc[node * 64 + (i & 63)] = 0.f;
    }
    for (int i = tid; i < 32 * 4; i += 256) {
        int node = base + (i >> 2);
        if (node < n) g_denom[node * 4 + (i & 3)] = 0.f;
    }

    int ln = tid >> 6;   // 0..3 local node within group
    int col = tid & 63;
    float blc = bl[col], brc = br[col];

    for (int g = 0; g < 8; g++) {
        __syncthreads();
        int nn = base + g * 4 + ln;
        sx[tid] = (nn < n) ? x[nn * 64 + col] : 0.f;
        __syncthreads();
        if (nn < n) {
            float sl = 0.f, sr = 0.f;
            const float* xv = sx + ln * 64;
#pragma unroll
            for (int c = 0; c < 64; c++) {
                float xc = xv[c];
                sl = fmaf(xc, sWl[c * 64 + col], sl);
                sr = fmaf(xc, sWr[c * 64 + col], sr);
            }
            g_xl[nn * 64 + col] = sl + blc;
            g_xr[nn * 64 + col] = sr + brc;
        }
    }
}

// K2: per-edge attention logits -> a_exp, accumulate softmax denominators.
// Softmax max-shift is dropped: shift-invariant and logits are O(0.1) here.
__global__ void edge_logit_kernel(const int* __restrict__ src, const int* __restrict__ dst,
                                  const float* __restrict__ att, int E) {
    __shared__ float satt[64];
    if (threadIdx.x < 64) satt[threadIdx.x] = att[threadIdx.x];
    __syncthreads();
    int e = blockIdx.x * blockDim.x + threadIdx.x;
    if (e >= E) return;
    int s = src[e], d = dst[e];
    const float4* xls = reinterpret_cast<const float4*>(g_xl) + s * 16;
    const float4* xrd = reinterpret_cast<const float4*>(g_xr) + d * 16;
    float logit[4] = {0.f, 0.f, 0.f, 0.f};
#pragma unroll
    for (int q = 0; q < 16; q++) {
        float4 a = xls[q];
        float4 b = xrd[q];
        int h = q >> 2;
        float v0 = a.x + b.x, v1 = a.y + b.y, v2 = a.z + b.z, v3 = a.w + b.w;
        v0 = v0 > 0.f ? v0 : NEG_SLOPE * v0;
        v1 = v1 > 0.f ? v1 : NEG_SLOPE * v1;
        v2 = v2 > 0.f ? v2 : NEG_SLOPE * v2;
        v3 = v3 > 0.f ? v3 : NEG_SLOPE * v3;
        logit[h] = fmaf(v0, satt[q * 4 + 0], logit[h]);
        logit[h] = fmaf(v1, satt[q * 4 + 1], logit[h]);
        logit[h] = fmaf(v2, satt[q * 4 + 2], logit[h]);
        logit[h] = fmaf(v3, satt[q * 4 + 3], logit[h]);
    }
    float e0 = expf(logit[0]), e1 = expf(logit[1]), e2 = expf(logit[2]), e3 = expf(logit[3]);
    reinterpret_cast<float4*>(g_aexp)[e] = make_float4(e0, e1, e2, e3);
    red_add_v4(&g_denom[d * 4], e0, e1, e2, e3);
}

// K3: per-edge weighted scatter of source messages into acc.
__global__ void edge_aggr_kernel(const int* __restrict__ src, const int* __restrict__ dst, int E) {
    int e = blockIdx.x * blockDim.x + threadIdx.x;
    if (e >= E) return;
    int s = src[e], d = dst[e];
    float4 ae = reinterpret_cast<const float4*>(g_aexp)[e];
    float4 dn = reinterpret_cast<const float4*>(g_denom)[d];
    float alpha0 = ae.x / dn.x, alpha1 = ae.y / dn.y, alpha2 = ae.z / dn.z, alpha3 = ae.w / dn.w;
    const float4* xls = reinterpret_cast<const float4*>(g_xl) + s * 16;
    float* accp = g_acc + d * 64;
#pragma unroll
    for (int q = 0; q < 16; q++) {
        float4 v = xls[q];
        float a = (q < 4) ? alpha0 : (q < 8) ? alpha1 : (q < 12) ? alpha2 : alpha3;
        red_add_v4(accp + q * 4, a * v.x, a * v.y, a * v.z, a * v.w);
    }
}

// K4: out = elu(LN(acc + bias + x)). One warp per node, 2 channels per lane.
__global__ void epilogue_kernel(const float* __restrict__ x, const float* __restrict__ bias,
                                const float* __restrict__ gamma, const float* __restrict__ beta,
                                float* __restrict__ out, int n) {
    int warp = (blockIdx.x * blockDim.x + threadIdx.x) >> 5;
    int lane = threadIdx.x & 31;
    if (warp >= n) return;
    int i0 = warp * 64 + lane;
    int i1 = i0 + 32;
    float v0 = g_acc[i0] + bias[lane] + x[i0];
    float v1 = g_acc[i1] + bias[lane + 32] + x[i1];
    float sum = v0 + v1;
    float ssq = v0 * v0 + v1 * v1;
#pragma unroll
    for (int o = 16; o; o >>= 1) {
        sum += __shfl_xor_sync(0xFFFFFFFFu, sum, o);
        ssq += __shfl_xor_sync(0xFFFFFFFFu, ssq, o);
    }
    float mean = sum * (1.f / 64.f);
    float var = ssq * (1.f / 64.f) - mean * mean;
    float rstd = rsqrtf(var + LN_EPS);
    float o0 = (v0 - mean) * rstd * gamma[lane] + beta[lane];
    float o1 = (v1 - mean) * rstd * gamma[lane + 32] + beta[lane + 32];
    out[i0] = o0 > 0.f ? o0 : expm1f(o0);
    out[i1] = o1 > 0.f ? o1 : expm1f(o1);
}

extern "C" void kernel_launch(void* const* d_in, const int* in_sizes, int n_in,
                              void* d_out, int out_size) {
    const float* x     = (const float*)d_in[0];
    const int*   ei    = (const int*)  d_in[1];
    const float* Wl    = (const float*)d_in[2];
    const float* bl    = (const float*)d_in[3];
    const float* Wr    = (const float*)d_in[4];
    const float* br    = (const float*)d_in[5];
    const float* att   = (const float*)d_in[6];
    const float* bias  = (const float*)d_in[7];
    const float* gamma = (const float*)d_in[8];
    const float* beta  = (const float*)d_in[9];
    float* out = (float*)d_out;

    int n = in_sizes[0] / 64;
    int E = in_sizes[1] / 2;
    const int* src = ei;
    const int* dst = ei + E;

    linear_kernel<<<(n + 31) / 32, 256>>>(x, Wl, bl, Wr, br, n);
    edge_logit_kernel<<<(E + 255) / 256, 256>>>(src, dst, att, E);
    edge_aggr_kernel<<<(E + 255) / 256, 256>>>(src, dst, E);
    epilogue_kernel<<<((long long)n * 32 + 255) / 256, 256>>>(x, bias, gamma, beta, out, n);
}

// round 2
// speedup vs baseline: 1.4479x; 1.4479x over previous
#include <cuda_runtime.h>

#define NEG_SLOPE 0.2f
#define LN_EPS 1e-5f

static const int MAXN = 50000;
static const int MAXE = 800000;

// Scratch (allocation-free: __device__ globals)
__device__ float g_xl[MAXN * 64];
__device__ float g_xr[MAXN * 64];
__device__ int   g_deg[MAXN];
__device__ int   g_ptr[MAXN + 1];
__device__ int   g_fill[MAXN];
__device__ int   g_csrc[MAXE];

// K1: xl = x@Wl + bl, xr = x@Wr + br. Also zeroes g_deg for this block's nodes.
__global__ void linear_kernel(const float* __restrict__ x,
                              const float* __restrict__ Wl, const float* __restrict__ bl,
                              const float* __restrict__ Wr, const float* __restrict__ br,
                              int n) {
    __shared__ float sWl[64 * 64];
    __shared__ float sWr[64 * 64];
    __shared__ float sx[4 * 64];
    int tid = threadIdx.x;
    for (int i = tid; i < 4096; i += 256) { sWl[i] = Wl[i]; sWr[i] = Wr[i]; }

    int base = blockIdx.x * 32;
    if (tid < 32) {
        int node = base + tid;
        if (node < n) g_deg[node] = 0;
    }

    int ln = tid >> 6;   // 0..3 local node within group of 4
    int col = tid & 63;
    float blc = bl[col], brc = br[col];

    for (int g = 0; g < 8; g++) {
        __syncthreads();
        int nn = base + g * 4 + ln;
        sx[tid] = (nn < n) ? x[nn * 64 + col] : 0.f;
        __syncthreads();
        if (nn < n) {
            float sl = 0.f, sr = 0.f;
            const float* xv = sx + ln * 64;
#pragma unroll
            for (int c = 0; c < 64; c++) {
                float xc = xv[c];
                sl = fmaf(xc, sWl[c * 64 + col], sl);
                sr = fmaf(xc, sWr[c * 64 + col], sr);
            }
            g_xl[nn * 64 + col] = sl + blc;
            g_xr[nn * 64 + col] = sr + brc;
        }
    }
}

// K2: in-degree histogram.
__global__ void hist_kernel(const int* __restrict__ dst, int E) {
    int e = blockIdx.x * blockDim.x + threadIdx.x;
    if (e < E) atomicAdd(&g_deg[dst[e]], 1);
}

// K3: exclusive prefix sum over g_deg -> g_ptr, g_fill. Single block, 1024 threads.
__global__ void scan_kernel(int n) {
    __shared__ int sh[1024];
    __shared__ int s_carry;
    int tid = threadIdx.x;
    if (tid == 0) s_carry = 0;
    __syncthreads();
    for (int base = 0; base < n; base += 1024) {
        int v = (base + tid < n) ? g_deg[base + tid] : 0;
        sh[tid] = v;
        __syncthreads();
        for (int off = 1; off < 1024; off <<= 1) {
            int t = (tid >= off) ? sh[tid - off] : 0;
            __syncthreads();
            sh[tid] += t;
            __syncthreads();
        }
        int carry = s_carry;
        int excl = carry + sh[tid] - v;
        if (base + tid < n) { g_ptr[base + tid] = excl; g_fill[base + tid] = excl; }
        __syncthreads();
        if (tid == 1023) s_carry = carry + sh[1023];
        __syncthreads();
    }
    if (tid == 0) g_ptr[n] = s_carry;
}

// K4: scatter edge sources into CSR order by dst.
__global__ void scatter_kernel(const int* __restrict__ src, const int* __restrict__ dst, int E) {
    int e = blockIdx.x * blockDim.x + threadIdx.x;
    if (e >= E) return;
    int d = dst[e];
    int p = atomicAdd(&g_fill[d], 1);
    g_csrc[p] = src[e];
}

// K5: fused per-node GAT aggregation + bias + residual + LayerNorm + ELU.
// One warp per destination node; 2 channels per lane (float2, coalesced).
// Head h = channels [16h,16h+16) -> lane group l>>3 owns one head's partials.
__global__ void gat_node_kernel(const float* __restrict__ x, const float* __restrict__ att,
                                const float* __restrict__ bias, const float* __restrict__ gamma,
                                const float* __restrict__ beta, float* __restrict__ out, int n) {
    int warp = (blockIdx.x * blockDim.x + threadIdx.x) >> 5;
    int lane = threadIdx.x & 31;
    if (warp >= n) return;
    int d = warp;
    int i0 = d * 64 + 2 * lane;

    float2 xr2  = *reinterpret_cast<const float2*>(g_xr + i0);
    float2 attv = *reinterpret_cast<const float2*>(att + 2 * lane);

    int start = g_ptr[d], end = g_ptr[d + 1];
    float accx = 0.f, accy = 0.f, denom = 0.f;

    for (int base = start; base < end; base += 32) {
        int cnt = min(32, end - base);
        int sv = (lane < cnt) ? g_csrc[base + lane] : 0;

        // software-pipelined gather of xl[src]
        int s0 = __shfl_sync(0xFFFFFFFFu, sv, 0);
        float2 cur = *reinterpret_cast<const float2*>(g_xl + s0 * 64 + 2 * lane);
        for (int j = 0; j < cnt; j++) {
            float2 nxt = cur;
            if (j + 1 < cnt) {
                int s = __shfl_sync(0xFFFFFFFFu, sv, j + 1);
                nxt = *reinterpret_cast<const float2*>(g_xl + s * 64 + 2 * lane);
            }
            float vx = cur.x + xr2.x, vy = cur.y + xr2.y;
            vx = vx > 0.f ? vx : NEG_SLOPE * vx;
            vy = vy > 0.f ? vy : NEG_SLOPE * vy;
            float p = fmaf(vx, attv.x, vy * attv.y);
            // reduce over 8-lane head group (lanes are 8-aligned per head)
            p += __shfl_xor_sync(0xFFFFFFFFu, p, 1);
            p += __shfl_xor_sync(0xFFFFFFFFu, p, 2);
            p += __shfl_xor_sync(0xFFFFFFFFu, p, 4);
            float ee = __expf(p);
            denom = denom + ee;
            accx = fmaf(ee, cur.x, accx);
            accy = fmaf(ee, cur.y, accy);
            cur = nxt;
        }
    }

    float inv = (end > start) ? 1.f / denom : 0.f;

    float2 xres = *reinterpret_cast<const float2*>(x + i0);
    float2 b2   = *reinterpret_cast<const float2*>(bias + 2 * lane);
    float v0 = fmaf(accx, inv, b2.x + xres.x);
    float v1 = fmaf(accy, inv, b2.y + xres.y);

    float sum = v0 + v1;
    float ssq = v0 * v0 + v1 * v1;
#pragma unroll
    for (int o = 16; o; o >>= 1) {
        sum += __shfl_xor_sync(0xFFFFFFFFu, sum, o);
        ssq += __shfl_xor_sync(0xFFFFFFFFu, ssq, o);
    }
    float mean = sum * (1.f / 64.f);
    float var  = ssq * (1.f / 64.f) - mean * mean;
    float rstd = rsqrtf(var + LN_EPS);

    float2 g2  = *reinterpret_cast<const float2*>(gamma + 2 * lane);
    float2 be2 = *reinterpret_cast<const float2*>(beta + 2 * lane);
    float o0 = fmaf((v0 - mean) * rstd, g2.x, be2.x);
    float o1 = fmaf((v1 - mean) * rstd, g2.y, be2.y);
    float2 r;
    r.x = o0 > 0.f ? o0 : expm1f(o0);
    r.y = o1 > 0.f ? o1 : expm1f(o1);
    *reinterpret_cast<float2*>(out + i0) = r;
}

extern "C" void kernel_launch(void* const* d_in, const int* in_sizes, int n_in,
                              void* d_out, int out_size) {
    const float* x     = (const float*)d_in[0];
    const int*   ei    = (const int*)  d_in[1];
    const float* Wl    = (const float*)d_in[2];
    const float* bl    = (const float*)d_in[3];
    const float* Wr    = (const float*)d_in[4];
    const float* br    = (const float*)d_in[5];
    const float* att   = (const float*)d_in[6];
    const float* bias  = (const float*)d_in[7];
    const float* gamma = (const float*)d_in[8];
    const float* beta  = (const float*)d_in[9];
    float* out = (float*)d_out;

    int n = in_sizes[0] / 64;
    int E = in_sizes[1] / 2;
    const int* src = ei;
    const int* dst = ei + E;

    linear_kernel<<<(n + 31) / 32, 256>>>(x, Wl, bl, Wr, br, n);
    hist_kernel<<<(E + 255) / 256, 256>>>(dst, E);
    scan_kernel<<<1, 1024>>>(n);
    scatter_kernel<<<(E + 255) / 256, 256>>>(src, dst, E);
    gat_node_kernel<<<((long long)n * 32 + 255) / 256, 256>>>(x, att, bias, gamma, beta, out, n);
}

// round 3
// speedup vs baseline: 2.1337x; 1.4736x over previous
#include <cuda_runtime.h>

#define NEG_SLOPE 0.2f
#define LN_EPS 1e-5f

static const int MAXN = 50000;
static const int MAXE = 800000;

// Scratch (allocation-free: __device__ globals)
__device__ float g_xl[MAXN * 64];
__device__ float g_xr[MAXN * 64];
__device__ int   g_deg[MAXN];
__device__ int   g_scan[MAXN];
__device__ int   g_ptr[MAXN + 1];
__device__ int   g_fill[MAXN];
__device__ int   g_csrc[MAXE];
__device__ int   g_tilesum[128];
__device__ int   g_tileoff[128];

// ---------------------------------------------------------------------------
// K1: xl = x@Wl + bl, xr = x@Wr + br using packed fma.rn.f32x2 (2 cols/lane).
// Block: 256 threads = 8 nodes/pass x 32 lanes; 8 passes -> 64 nodes/block.
// Also zeroes g_deg for this block's node range.
// ---------------------------------------------------------------------------
__global__ void linear_kernel(const float* __restrict__ x,
                              const float* __restrict__ Wl, const float* __restrict__ bl,
                              const float* __restrict__ Wr, const float* __restrict__ br,
                              int n) {
    __shared__ float sWl[64 * 64];
    __shared__ float sWr[64 * 64];
    __shared__ float sx[8 * 64];
    int tid = threadIdx.x;
    for (int i = tid; i < 4096; i += 256) { sWl[i] = Wl[i]; sWr[i] = Wr[i]; }

    int base = blockIdx.x * 64;
    if (tid < 64) {
        int node = base + tid;
        if (node < n) g_deg[node] = 0;
    }

    int ln = tid >> 5;       // 0..7 local node within pass
    int j  = tid & 31;       // lane -> output cols 2j, 2j+1
    float2 bl2 = *reinterpret_cast<const float2*>(bl + 2 * j);
    float2 br2 = *reinterpret_cast<const float2*>(br + 2 * j);

    for (int g = 0; g < 8; g++) {
        __syncthreads();
        int pbase = base + g * 8;
        // load 8 node rows (512 floats) cooperatively
        for (int i = tid; i < 512; i += 256) {
            int nn = pbase + (i >> 6);
            sx[i] = (nn < n) ? x[nn * 64 + (i & 63)] : 0.f;
        }
        __syncthreads();
        int nn = pbase + ln;
        if (nn < n) {
            unsigned long long accl = 0ull, accr = 0ull;
            const float* xv = sx + ln * 64;
            const unsigned long long* wl2 =
                reinterpret_cast<const unsigned long long*>(sWl + 2 * j);
            const unsigned long long* wr2 =
                reinterpret_cast<const unsigned long long*>(sWr + 2 * j);
#pragma unroll
            for (int c = 0; c < 64; c++) {
                float xc = xv[c];
                unsigned long long x2;
                asm("mov.b64 %0, {%1, %1};" : "=l"(x2) : "f"(xc));
                asm("fma.rn.f32x2 %0, %1, %2, %0;" : "+l"(accl) : "l"(x2), "l"(wl2[c * 32]));
                asm("fma.rn.f32x2 %0, %1, %2, %0;" : "+l"(accr) : "l"(x2), "l"(wr2[c * 32]));
            }
            float l0, l1, r0, r1;
            asm("mov.b64 {%0, %1}, %2;" : "=f"(l0), "=f"(l1) : "l"(accl));
            asm("mov.b64 {%0, %1}, %2;" : "=f"(r0), "=f"(r1) : "l"(accr));
            float2 outl = make_float2(l0 + bl2.x, l1 + bl2.y);
            float2 outr = make_float2(r0 + br2.x, r1 + br2.y);
            *reinterpret_cast<float2*>(g_xl + nn * 64 + 2 * j) = outl;
            *reinterpret_cast<float2*>(g_xr + nn * 64 + 2 * j) = outr;
        }
    }
}

// ---------------------------------------------------------------------------
// K2: in-degree histogram (4 edges/thread for MLP).
// ---------------------------------------------------------------------------
__global__ void hist_kernel(const int* __restrict__ dst, int E) {
    int i = (blockIdx.x * blockDim.x + threadIdx.x) * 4;
    if (i + 3 < E) {
        int4 d4 = *reinterpret_cast<const int4*>(dst + i);
        atomicAdd(&g_deg[d4.x], 1);
        atomicAdd(&g_deg[d4.y], 1);
        atomicAdd(&g_deg[d4.z], 1);
        atomicAdd(&g_deg[d4.w], 1);
    } else {
        for (int e = i; e < E; e++) atomicAdd(&g_deg[dst[e]], 1);
    }
}

// ---------------------------------------------------------------------------
// K3a: per-tile (1024) inclusive scan of g_deg -> g_scan; tile totals.
// ---------------------------------------------------------------------------
__global__ void scan1_kernel(int n) {
    __shared__ int wsum[32];
    int gid = blockIdx.x * 1024 + threadIdx.x;
    int lane = threadIdx.x & 31, wid = threadIdx.x >> 5;
    int v = (gid < n) ? g_deg[gid] : 0;
    int s = v;
#pragma unroll
    for (int o = 1; o < 32; o <<= 1) {
        int t = __shfl_up_sync(0xFFFFFFFFu, s, o);
        if (lane >= o) s += t;
    }
    if (lane == 31) wsum[wid] = s;
    __syncthreads();
    if (wid == 0) {
        int w = wsum[lane];
#pragma unroll
        for (int o = 1; o < 32; o <<= 1) {
            int t = __shfl_up_sync(0xFFFFFFFFu, w, o);
            if (lane >= o) w += t;
        }
        wsum[lane] = w;
    }
    __syncthreads();
    int incl = s + (wid ? wsum[wid - 1] : 0);
    if (gid < n) g_scan[gid] = incl;
    if (threadIdx.x == 1023) g_tilesum[blockIdx.x] = incl;
}

// K3b: exclusive scan of tile sums (single small block).
__global__ void scan2_kernel(int ntiles) {
    __shared__ int sh[128];
    int t = threadIdx.x;
    int v = (t < ntiles) ? g_tilesum[t] : 0;
    sh[t] = v;
    __syncthreads();
#pragma unroll
    for (int o = 1; o < 128; o <<= 1) {
        int tmp = (t >= o) ? sh[t - o] : 0;
        __syncthreads();
        sh[t] += tmp;
        __syncthreads();
    }
    if (t < ntiles) g_tileoff[t] = sh[t] - v;
}

// K3c: apply offsets -> g_ptr (exclusive), g_fill.
__global__ void scan3_kernel(int n) {
    int gid = blockIdx.x * 1024 + threadIdx.x;
    if (gid < n) {
        int off  = g_tileoff[blockIdx.x];
        int incl = g_scan[gid] + off;
        int excl = incl - g_deg[gid];
        g_ptr[gid]  = excl;
        g_fill[gid] = excl;
        if (gid == n - 1) g_ptr[n] = incl;
    }
}

// ---------------------------------------------------------------------------
// K4: scatter edge sources into CSR order by dst (4 edges/thread).
// ---------------------------------------------------------------------------
__global__ void scatter_kernel(const int* __restrict__ src, const int* __restrict__ dst, int E) {
    int i = (blockIdx.x * blockDim.x + threadIdx.x) * 4;
    if (i + 3 < E) {
        int4 d4 = *reinterpret_cast<const int4*>(dst + i);
        int4 s4 = *reinterpret_cast<const int4*>(src + i);
        int p0 = atomicAdd(&g_fill[d4.x], 1);
        int p1 = atomicAdd(&g_fill[d4.y], 1);
        int p2 = atomicAdd(&g_fill[d4.z], 1);
        int p3 = atomicAdd(&g_fill[d4.w], 1);
        g_csrc[p0] = s4.x;
        g_csrc[p1] = s4.y;
        g_csrc[p2] = s4.z;
        g_csrc[p3] = s4.w;
    } else {
        for (int e = i; e < E; e++) {
            int p = atomicAdd(&g_fill[dst[e]], 1);
            g_csrc[p] = src[e];
        }
    }
}

// ---------------------------------------------------------------------------
// K5: fused per-node GAT aggregation + bias + residual + LayerNorm + ELU.
// One warp per destination node; 2 channels per lane; 4 edges in flight.
// ---------------------------------------------------------------------------
__global__ void gat_node_kernel(const float* __restrict__ x, const float* __restrict__ att,
                                const float* __restrict__ bias, const float* __restrict__ gamma,
                                const float* __restrict__ beta, float* __restrict__ out, int n) {
    int warp = (blockIdx.x * blockDim.x + threadIdx.x) >> 5;
    int lane = threadIdx.x & 31;
    if (warp >= n) return;
    int d = warp;
    int i0 = d * 64 + 2 * lane;

    float2 xr2  = *reinterpret_cast<const float2*>(g_xr + i0);
    float2 attv = *reinterpret_cast<const float2*>(att + 2 * lane);

    int start = g_ptr[d], end = g_ptr[d + 1];
    float accx = 0.f, accy = 0.f, denom = 0.f;

    for (int base = start; base < end; base += 32) {
        int cnt = min(32, end - base);
        int sv = (lane < cnt) ? g_csrc[base + lane] : 0;

        for (int j = 0; j < cnt; j += 4) {
            float2 c[4];
            float  w[4];
#pragma unroll
            for (int k = 0; k < 4; k++) {
                int jj = j + k;
                int s = __shfl_sync(0xFFFFFFFFu, sv, jj);
                c[k] = *reinterpret_cast<const float2*>(g_xl + s * 64 + 2 * lane);
                w[k] = (jj < cnt) ? 1.f : 0.f;
            }
            float p[4];
#pragma unroll
            for (int k = 0; k < 4; k++) {
                float vx = c[k].x + xr2.x, vy = c[k].y + xr2.y;
                vx = vx > 0.f ? vx : NEG_SLOPE * vx;
                vy = vy > 0.f ? vy : NEG_SLOPE * vy;
                p[k] = fmaf(vx, attv.x, vy * attv.y);
            }
#pragma unroll
            for (int k = 0; k < 4; k++) p[k] += __shfl_xor_sync(0xFFFFFFFFu, p[k], 1);
#pragma unroll
            for (int k = 0; k < 4; k++) p[k] += __shfl_xor_sync(0xFFFFFFFFu, p[k], 2);
#pragma unroll
            for (int k = 0; k < 4; k++) p[k] += __shfl_xor_sync(0xFFFFFFFFu, p[k], 4);
#pragma unroll
            for (int k = 0; k < 4; k++) {
                float ee = __expf(p[k]) * w[k];
                denom += ee;
                accx = fmaf(ee, c[k].x, accx);
                accy = fmaf(ee, c[k].y, accy);
            }
        }
    }

    float inv = (end > start) ? 1.f / denom : 0.f;

    float2 xres = *reinterpret_cast<const float2*>(x + i0);
    float2 b2   = *reinterpret_cast<const float2*>(bias + 2 * lane);
    float v0 = fmaf(accx, inv, b2.x + xres.x);
    float v1 = fmaf(accy, inv, b2.y + xres.y);

    float sum = v0 + v1;
    float ssq = v0 * v0 + v1 * v1;
#pragma unroll
    for (int o = 16; o; o >>= 1) {
        sum += __shfl_xor_sync(0xFFFFFFFFu, sum, o);
        ssq += __shfl_xor_sync(0xFFFFFFFFu, ssq, o);
    }
    float mean = sum * (1.f / 64.f);
    float var  = ssq * (1.f / 64.f) - mean * mean;
    float rstd = rsqrtf(var + LN_EPS);

    float2 g2  = *reinterpret_cast<const float2*>(gamma + 2 * lane);
    float2 be2 = *reinterpret_cast<const float2*>(beta + 2 * lane);
    float o0 = fmaf((v0 - mean) * rstd, g2.x, be2.x);
    float o1 = fmaf((v1 - mean) * rstd, g2.y, be2.y);
    float2 r;
    r.x = o0 > 0.f ? o0 : expm1f(o0);
    r.y = o1 > 0.f ? o1 : expm1f(o1);
    *reinterpret_cast<float2*>(out + i0) = r;
}

extern "C" void kernel_launch(void* const* d_in, const int* in_sizes, int n_in,
                              void* d_out, int out_size) {
    const float* x     = (const float*)d_in[0];
    const int*   ei    = (const int*)  d_in[1];
    const float* Wl    = (const float*)d_in[2];
    const float* bl    = (const float*)d_in[3];
    const float* Wr    = (const float*)d_in[4];
    const float* br    = (const float*)d_in[5];
    const float* att   = (const float*)d_in[6];
    const float* bias  = (const float*)d_in[7];
    const float* gamma = (const float*)d_in[8];
    const float* beta  = (const float*)d_in[9];
    float* out = (float*)d_out;

    int n = in_sizes[0] / 64;
    int E = in_sizes[1] / 2;
    const int* src = ei;
    const int* dst = ei + E;
    int ntiles = (n + 1023) / 1024;

    linear_kernel<<<(n + 63) / 64, 256>>>(x, Wl, bl, Wr, br, n);
    hist_kernel<<<(E / 4 + 255) / 256 + 1, 256>>>(dst, E);
    scan1_kernel<<<ntiles, 1024>>>(n);
    scan2_kernel<<<1, 128>>>(ntiles);
    scan3_kernel<<<ntiles, 1024>>>(n);
    scatter_kernel<<<(E / 4 + 255) / 256 + 1, 256>>>(src, dst, E);
    gat_node_kernel<<<((long long)n * 32 + 255) / 256, 256>>>(x, att, bias, gamma, beta, out, n);
}

// round 4
// speedup vs baseline: 2.9831x; 1.3981x over previous
#include <cuda_runtime.h>

#define NEG_SLOPE 0.2f
#define LN_EPS 1e-5f

static const int MAXN = 50000;
static const int MAXE = 800000;

// Scratch (allocation-free: __device__ globals; BSS zero-init at load)
__device__ float g_xl[MAXN * 64];
__device__ float g_xr[MAXN * 64];
__device__ int   g_deg[MAXN];      // invariant: zero at kernel_launch entry
__device__ int   g_scan[MAXN];
__device__ int   g_ptr[MAXN + 1];
__device__ int   g_fill[MAXN];
__device__ int   g_csrc[MAXE];
__device__ int   g_tilesum[128];

// ---------------------------------------------------------------------------
// K1: xl = x@Wl + bl, xr = x@Wr + br.  8 nodes per warp (weights amortized in
// registers, fma.rn.f32x2 packed), 64 nodes per 256-thread block.
// Tail: fused in-degree histogram (g_deg must be zero at entry; scan3 restores).
// ---------------------------------------------------------------------------
__global__ void linear_hist_kernel(const float* __restrict__ x,
                                   const float* __restrict__ Wl, const float* __restrict__ bl,
                                   const float* __restrict__ Wr, const float* __restrict__ br,
                                   const int* __restrict__ dst,
                                   int n, int E) {
    __shared__ __align__(16) float sWl[64 * 64];
    __shared__ __align__(16) float sWr[64 * 64];
    __shared__ __align__(16) float sx[64 * 64];
    int tid = threadIdx.x;
    for (int i = tid; i < 4096; i += 256) { sWl[i] = Wl[i]; sWr[i] = Wr[i]; }

    int base = blockIdx.x * 64;
    // stage 64 node rows of x (zero-padded at the tail)
    for (int i = tid; i < 4096; i += 256) {
        int nn = base + (i >> 6);
        sx[i] = (nn < n) ? x[nn * 64 + (i & 63)] : 0.f;
    }
    __syncthreads();

    int w = tid >> 5;        // warp 0..7 -> nodes base + 8w .. +8
    int j = tid & 31;        // lane -> output cols 2j, 2j+1
    {
        unsigned long long accl[8], accr[8];
#pragma unroll
        for (int k = 0; k < 8; k++) { accl[k] = 0ull; accr[k] = 0ull; }

        const unsigned long long* wl2 = reinterpret_cast<const unsigned long long*>(sWl + 2 * j);
        const unsigned long long* wr2 = reinterpret_cast<const unsigned long long*>(sWr + 2 * j);
        const float* xv = sx + (w * 8) * 64;

#pragma unroll 8
        for (int c = 0; c < 64; c++) {
            unsigned long long wl = wl2[c * 32];
            unsigned long long wr = wr2[c * 32];
#pragma unroll
            for (int k = 0; k < 8; k++) {
                float xc = xv[k * 64 + c];
                unsigned long long x2;
                asm("mov.b64 %0, {%1, %1};" : "=l"(x2) : "f"(xc));
                asm("fma.rn.f32x2 %0, %1, %2, %0;" : "+l"(accl[k]) : "l"(x2), "l"(wl));
                asm("fma.rn.f32x2 %0, %1, %2, %0;" : "+l"(accr[k]) : "l"(x2), "l"(wr));
            }
        }

        float2 bl2 = *reinterpret_cast<const float2*>(bl + 2 * j);
        float2 br2 = *reinterpret_cast<const float2*>(br + 2 * j);
#pragma unroll
        for (int k = 0; k < 8; k++) {
            int nn = base + w * 8 + k;
            if (nn < n) {
                float l0, l1, r0, r1;
                asm("mov.b64 {%0, %1}, %2;" : "=f"(l0), "=f"(l1) : "l"(accl[k]));
                asm("mov.b64 {%0, %1}, %2;" : "=f"(r0), "=f"(r1) : "l"(accr[k]));
                *reinterpret_cast<float2*>(g_xl + nn * 64 + 2 * j) =
                    make_float2(l0 + bl2.x, l1 + bl2.y);
                *reinterpret_cast<float2*>(g_xr + nn * 64 + 2 * j) =
                    make_float2(r0 + br2.x, r1 + br2.y);
            }
        }
    }

    // fused in-degree histogram (grid-stride over edges)
    int stride = gridDim.x * 256;
    for (int e = blockIdx.x * 256 + tid; e < E; e += stride)
        atomicAdd(&g_deg[dst[e]], 1);
}

// ---------------------------------------------------------------------------
// K2: per-tile (1024) inclusive scan of g_deg -> g_scan; tile totals.
// ---------------------------------------------------------------------------
__global__ void scan1_kernel(int n) {
    __shared__ int wsum[32];
    int gid = blockIdx.x * 1024 + threadIdx.x;
    int lane = threadIdx.x & 31, wid = threadIdx.x >> 5;
    int v = (gid < n) ? g_deg[gid] : 0;
    int s = v;
#pragma unroll
    for (int o = 1; o < 32; o <<= 1) {
        int t = __shfl_up_sync(0xFFFFFFFFu, s, o);
        if (lane >= o) s += t;
    }
    if (lane == 31) wsum[wid] = s;
    __syncthreads();
    if (wid == 0) {
        int wv = wsum[lane];
#pragma unroll
        for (int o = 1; o < 32; o <<= 1) {
            int t = __shfl_up_sync(0xFFFFFFFFu, wv, o);
            if (lane >= o) wv += t;
        }
        wsum[lane] = wv;
    }
    __syncthreads();
    int incl = s + (wid ? wsum[wid - 1] : 0);
    if (gid < n) g_scan[gid] = incl;
    if (threadIdx.x == 1023) g_tilesum[blockIdx.x] = incl;
}

// ---------------------------------------------------------------------------
// K3: per-block tile-offset (warp sum over preceding tile sums), then apply:
//     g_ptr (exclusive), g_fill; re-zero g_deg to restore the invariant.
// ---------------------------------------------------------------------------
__global__ void scan3_kernel(int n) {
    __shared__ int s_off;
    int t = threadIdx.x;
    if (t < 32) {
        int acc = 0;
        for (int i = t; i < blockIdx.x; i += 32) acc += g_tilesum[i];
#pragma unroll
        for (int o = 16; o; o >>= 1) acc += __shfl_xor_sync(0xFFFFFFFFu, acc, o);
        if (t == 0) s_off = acc;
    }
    __syncthreads();
    int gid = blockIdx.x * 1024 + t;
    if (gid < n) {
        int incl = g_scan[gid] + s_off;
        int excl = incl - g_deg[gid];
        g_ptr[gid]  = excl;
        g_fill[gid] = excl;
        g_deg[gid]  = 0;            // restore invariant for next launch
        if (gid == n - 1) g_ptr[n] = incl;
    }
}

// ---------------------------------------------------------------------------
// K4: scatter edge sources into CSR order by dst (4 edges/thread).
// ---------------------------------------------------------------------------
__global__ void scatter_kernel(const int* __restrict__ src, const int* __restrict__ dst, int E) {
    int i = (blockIdx.x * blockDim.x + threadIdx.x) * 4;
    if (i + 3 < E) {
        int4 d4 = *reinterpret_cast<const int4*>(dst + i);
        int4 s4 = *reinterpret_cast<const int4*>(src + i);
        int p0 = atomicAdd(&g_fill[d4.x], 1);
        int p1 = atomicAdd(&g_fill[d4.y], 1);
        int p2 = atomicAdd(&g_fill[d4.z], 1);
        int p3 = atomicAdd(&g_fill[d4.w], 1);
        g_csrc[p0] = s4.x;
        g_csrc[p1] = s4.y;
        g_csrc[p2] = s4.z;
        g_csrc[p3] = s4.w;
    } else {
        for (int e = i; e < E; e++) {
            int p = atomicAdd(&g_fill[dst[e]], 1);
            g_csrc[p] = src[e];
        }
    }
}

// ---------------------------------------------------------------------------
// K5: fused per-node GAT aggregation + bias + residual + LayerNorm + ELU.
// One warp per destination node; 2 channels per lane; 4 edges in flight.
// ---------------------------------------------------------------------------
__global__ void gat_node_kernel(const float* __restrict__ x, const float* __restrict__ att,
                                const float* __restrict__ bias, const float* __restrict__ gamma,
                                const float* __restrict__ beta, float* __restrict__ out, int n) {
    int warp = (blockIdx.x * blockDim.x + threadIdx.x) >> 5;
    int lane = threadIdx.x & 31;
    if (warp >= n) return;
    int d = warp;
    int i0 = d * 64 + 2 * lane;

    float2 xr2  = __ldg(reinterpret_cast<const float2*>(g_xr + i0));
    float2 attv = *reinterpret_cast<const float2*>(att + 2 * lane);

    int start = __ldg(&g_ptr[d]), end = __ldg(&g_ptr[d + 1]);
    float accx = 0.f, accy = 0.f, denom = 0.f;

    for (int base = start; base < end; base += 32) {
        int cnt = min(32, end - base);
        int sv = (lane < cnt) ? __ldg(&g_csrc[base + lane]) : 0;

        for (int j = 0; j < cnt; j += 4) {
            float2 c[4];
            float  w[4];
#pragma unroll
            for (int k = 0; k < 4; k++) {
                int jj = j + k;
                int s = __shfl_sync(0xFFFFFFFFu, sv, jj);
                c[k] = __ldg(reinterpret_cast<const float2*>(g_xl + s * 64 + 2 * lane));
                w[k] = (jj < cnt) ? 1.f : 0.f;
            }
            float p[4];
#pragma unroll
            for (int k = 0; k < 4; k++) {
                float vx = c[k].x + xr2.x, vy = c[k].y + xr2.y;
                vx = vx > 0.f ? vx : NEG_SLOPE * vx;
                vy = vy > 0.f ? vy : NEG_SLOPE * vy;
                p[k] = fmaf(vx, attv.x, vy * attv.y);
            }
#pragma unroll
            for (int k = 0; k < 4; k++) p[k] += __shfl_xor_sync(0xFFFFFFFFu, p[k], 1);
#pragma unroll
            for (int k = 0; k < 4; k++) p[k] += __shfl_xor_sync(0xFFFFFFFFu, p[k], 2);
#pragma unroll
            for (int k = 0; k < 4; k++) p[k] += __shfl_xor_sync(0xFFFFFFFFu, p[k], 4);
#pragma unroll
            for (int k = 0; k < 4; k++) {
                float ee = __expf(p[k]) * w[k];
                denom += ee;
                accx = fmaf(ee, c[k].x, accx);
                accy = fmaf(ee, c[k].y, accy);
            }
        }
    }

    float inv = (end > start) ? 1.f / denom : 0.f;

    float2 xres = *reinterpret_cast<const float2*>(x + i0);
    float2 b2   = *reinterpret_cast<const float2*>(bias + 2 * lane);
    float v0 = fmaf(accx, inv, b2.x + xres.x);
    float v1 = fmaf(accy, inv, b2.y + xres.y);

    float sum = v0 + v1;
    float ssq = v0 * v0 + v1 * v1;
#pragma unroll
    for (int o = 16; o; o >>= 1) {
        sum += __shfl_xor_sync(0xFFFFFFFFu, sum, o);
        ssq += __shfl_xor_sync(0xFFFFFFFFu, ssq, o);
    }
    float mean = sum * (1.f / 64.f);
    float var  = ssq * (1.f / 64.f) - mean * mean;
    float rstd = rsqrtf(var + LN_EPS);

    float2 g2  = *reinterpret_cast<const float2*>(gamma + 2 * lane);
    float2 be2 = *reinterpret_cast<const float2*>(beta + 2 * lane);
    float o0 = fmaf((v0 - mean) * rstd, g2.x, be2.x);
    float o1 = fmaf((v1 - mean) * rstd, g2.y, be2.y);
    float2 r;
    r.x = o0 > 0.f ? o0 : expm1f(o0);
    r.y = o1 > 0.f ? o1 : expm1f(o1);
    *reinterpret_cast<float2*>(out + i0) = r;
}

extern "C" void kernel_launch(void* const* d_in, const int* in_sizes, int n_in,
                              void* d_out, int out_size) {
    const float* x     = (const float*)d_in[0];
    const int*   ei    = (const int*)  d_in[1];
    const float* Wl    = (const float*)d_in[2];
    const float* bl    = (const float*)d_in[3];
    const float* Wr    = (const float*)d_in[4];
    const float* br    = (const float*)d_in[5];
    const float* att   = (const float*)d_in[6];
    const float* bias  = (const float*)d_in[7];
    const float* gamma = (const float*)d_in[8];
    const float* beta  = (const float*)d_in[9];
    float* out = (float*)d_out;

    int n = in_sizes[0] / 64;
    int E = in_sizes[1] / 2;
    const int* src = ei;
    const int* dst = ei + E;
    int ntiles = (n + 1023) / 1024;

    linear_hist_kernel<<<(n + 63) / 64, 256>>>(x, Wl, bl, Wr, br, dst, n, E);
    scan1_kernel<<<ntiles, 1024>>>(n);
    scan3_kernel<<<ntiles, 1024>>>(n);
    scatter_kernel<<<(E / 4 + 255) / 256 + 1, 256>>>(src, dst, E);
    gat_node_kernel<<<((long long)n * 32 + 255) / 256, 256>>>(x, att, bias, gamma, beta, out, n);
}